// round 6
// baseline (speedup 1.0000x reference)
#include <cuda_runtime.h>
#include <cstdint>

#define BB 2
#define LL 256
#define HH 512
#define NHH 8
#define DHH 64

// ---------------- scratch (device globals; no allocation) ----------------
__device__ __align__(16) float g_K[BB*LL*HH];
__device__ __align__(16) float g_Q[BB*LL*HH];
__device__ __align__(16) float g_V[BB*LL*HH];
__device__ __align__(16) float g_T[BB*LL*NHH*HH];    // [m][n][h]  8 MB
__device__ __align__(16) float g_AC[BB*LL*NHH*LL];   // [m][n][j]  4 MB
__device__ __align__(16) float g_P[BB*LL*NHH*LL];    // [m][n][j]  4 MB
__device__ __align__(16) float g_CTX[BB*LL*HH];

// ---------------- f32x2 helpers ----------------
__device__ __forceinline__ unsigned long long ffma2(unsigned long long a,
                                                    unsigned long long b,
                                                    unsigned long long c) {
    unsigned long long d;
    asm("fma.rn.f32x2 %0, %1, %2, %3;" : "=l"(d) : "l"(a), "l"(b), "l"(c));
    return d;
}
__device__ __forceinline__ unsigned long long splat2(float a) {
    unsigned long long r;
    asm("mov.b64 %0, {%1, %1};" : "=l"(r) : "f"(a));
    return r;
}
__device__ __forceinline__ float2 unpack2(unsigned long long v) {
    float2 f;
    asm("mov.b64 {%0, %1}, %2;" : "=f"(f.x), "=f"(f.y) : "l"(v));
    return f;
}
__device__ __forceinline__ void cpasync16(uint32_t s, const void* g) {
    asm volatile("cp.async.cg.shared.global [%0], [%1], 16;\n" :: "r"(s), "l"(g));
}
__device__ __forceinline__ void cpasync_commit() {
    asm volatile("cp.async.commit_group;\n" ::: "memory");
}
template <int N>
__device__ __forceinline__ void cpasync_wait() {
    asm volatile("cp.async.wait_group %0;\n" :: "n"(N) : "memory");
}

// ---------------- 32x64-tile GEMM body: C[512,512] = A @ W + bias ----------------
// grid (8, 16): 128 blocks. 256 threads, 2x4 per-thread micro-tile, k-tile 32,
// register double-buffered, FMA2.
__device__ __forceinline__ void gemm32x64_body(const float* __restrict__ A,
                                               const float* __restrict__ W,
                                               const float* __restrict__ bias,
                                               float* __restrict__ C)
{
    __shared__ __align__(16) float As[32][34];   // [k][m]
    __shared__ __align__(16) float Bs[32][68];   // [k][n]

    const int tid = threadIdx.x;
    const int tx  = tid & 15;
    const int ty  = tid >> 4;
    const int row0 = blockIdx.y * 32;
    const int col0 = blockIdx.x * 64;

    const int lm = tid >> 3;          // A row 0..31
    const int lk = (tid & 7) * 4;     // A k offset 0..28
    const int wr = tid >> 4;          // W row
    const int wc = (tid & 15) * 4;    // W col offset

    float4 a0 = *(const float4*)&A[(row0 + lm) * 512 + lk];
    float4 b0 = *(const float4*)&W[(0  + wr) * 512 + col0 + wc];
    float4 b1 = *(const float4*)&W[(16 + wr) * 512 + col0 + wc];

    unsigned long long acc[2][2] = {};

    for (int kt = 0; kt < 512; kt += 32) {
        As[lk + 0][lm] = a0.x; As[lk + 1][lm] = a0.y;
        As[lk + 2][lm] = a0.z; As[lk + 3][lm] = a0.w;
        *(float4*)&Bs[wr][wc]      = b0;
        *(float4*)&Bs[wr + 16][wc] = b1;
        __syncthreads();

        if (kt + 32 < 512) {
            a0 = *(const float4*)&A[(row0 + lm) * 512 + kt + 32 + lk];
            b0 = *(const float4*)&W[(kt + 32 + wr) * 512 + col0 + wc];
            b1 = *(const float4*)&W[(kt + 48 + wr) * 512 + col0 + wc];
        }

        #pragma unroll
        for (int kk = 0; kk < 32; kk++) {
            float2 av = *(const float2*)&As[kk][ty * 2];
            ulonglong2 bp = *(const ulonglong2*)&Bs[kk][tx * 4];
            unsigned long long s0 = splat2(av.x);
            unsigned long long s1 = splat2(av.y);
            acc[0][0] = ffma2(s0, bp.x, acc[0][0]); acc[0][1] = ffma2(s0, bp.y, acc[0][1]);
            acc[1][0] = ffma2(s1, bp.x, acc[1][0]); acc[1][1] = ffma2(s1, bp.y, acc[1][1]);
        }
        __syncthreads();
    }

    float4 bb = *(const float4*)&bias[col0 + tx * 4];
    #pragma unroll
    for (int r = 0; r < 2; r++) {
        float2 p0 = unpack2(acc[r][0]);
        float2 p1 = unpack2(acc[r][1]);
        float4 o;
        o.x = p0.x + bb.x; o.y = p0.y + bb.y;
        o.z = p1.x + bb.z; o.w = p1.y + bb.w;
        *(float4*)&C[(row0 + ty * 2 + r) * 512 + col0 + tx * 4] = o;
    }
}

__global__ void proj_kernel(const float* __restrict__ key,
                            const float* __restrict__ query,
                            const float* __restrict__ value,
                            const float* __restrict__ Wk, const float* __restrict__ bk,
                            const float* __restrict__ Wq, const float* __restrict__ bq,
                            const float* __restrict__ Wv, const float* __restrict__ bv)
{
    const float *A, *W, *bias;
    float* C;
    if (blockIdx.z == 0)      { A = key;   W = Wk; bias = bk; C = g_K; }
    else if (blockIdx.z == 1) { A = query; W = Wq; bias = bq; C = g_Q; }
    else                      { A = value; W = Wv; bias = bv; C = g_V; }
    gemm32x64_body(A, W, bias, C);
}

__global__ void final_kernel(const float* __restrict__ Wf,
                             const float* __restrict__ bf,
                             float* __restrict__ out)
{
    gemm32x64_body(g_CTX, Wf, bf, out);
}

// ---------------- K=64 A@B^T body (tilde + AC) ----------------
// C[i][c] = sum_d (A[i*512+d] + avec[d]) * B[c*512+d],  i,c in [0,64)
__device__ __forceinline__ void nt64_body(const float* __restrict__ Arow0,
                                          const float* __restrict__ avec,
                                          const float* __restrict__ Brow0,
                                          float* __restrict__ Cbase, int ldc)
{
    __shared__ __align__(16) float As[16][68];
    __shared__ __align__(16) float Bs[16][68];

    const int tid = threadIdx.x;
    const int tx = tid & 15, ty = tid >> 4;
    const int lm = tid >> 2;
    const int lk = (tid & 3) * 4;

    unsigned long long acc[4][2] = {};

    for (int kt = 0; kt < 64; kt += 16) {
        float4 a4 = *(const float4*)&Arow0[lm * 512 + kt + lk];
        float4 vb = *(const float4*)&avec[kt + lk];
        a4.x += vb.x; a4.y += vb.y; a4.z += vb.z; a4.w += vb.w;
        As[lk + 0][lm] = a4.x; As[lk + 1][lm] = a4.y;
        As[lk + 2][lm] = a4.z; As[lk + 3][lm] = a4.w;
        float4 b4 = *(const float4*)&Brow0[lm * 512 + kt + lk];
        Bs[lk + 0][lm] = b4.x; Bs[lk + 1][lm] = b4.y;
        Bs[lk + 2][lm] = b4.z; Bs[lk + 3][lm] = b4.w;
        __syncthreads();

        #pragma unroll
        for (int kk = 0; kk < 16; kk++) {
            float4 av = *(const float4*)&As[kk][ty * 4];
            ulonglong2 bp = *(const ulonglong2*)&Bs[kk][tx * 4];
            unsigned long long s0 = splat2(av.x);
            unsigned long long s1 = splat2(av.y);
            unsigned long long s2 = splat2(av.z);
            unsigned long long s3 = splat2(av.w);
            acc[0][0] = ffma2(s0, bp.x, acc[0][0]); acc[0][1] = ffma2(s0, bp.y, acc[0][1]);
            acc[1][0] = ffma2(s1, bp.x, acc[1][0]); acc[1][1] = ffma2(s1, bp.y, acc[1][1]);
            acc[2][0] = ffma2(s2, bp.x, acc[2][0]); acc[2][1] = ffma2(s2, bp.y, acc[2][1]);
            acc[3][0] = ffma2(s3, bp.x, acc[3][0]); acc[3][1] = ffma2(s3, bp.y, acc[3][1]);
        }
        __syncthreads();
    }

    #pragma unroll
    for (int r = 0; r < 4; r++) {
        float2 p0 = unpack2(acc[r][0]);
        float2 p1 = unpack2(acc[r][1]);
        float4 o; o.x = p0.x; o.y = p0.y; o.z = p1.x; o.w = p1.y;
        *(float4*)&Cbase[(ty * 4 + r) * ldc + tx * 4] = o;
    }
}

// tilde: T[m][n][h] = sum_d (Q[m][n*64+d]+vpos[n*64+d]) * Wr[h][n*64+d]
__global__ void tilde_kernel(const float* __restrict__ Wr,
                             const float* __restrict__ vpos)
{
    const int h0 = blockIdx.x * 64;
    const int m0 = blockIdx.y * 64;
    const int n  = blockIdx.z;
    nt64_body(g_Q + m0 * 512 + n * 64, vpos + n * 64,
              Wr + h0 * 512 + n * 64,
              g_T + (m0 * 8 + n) * 512 + h0, 4096);
}

// AC: AC[m][n][j] = sum_d (Q[m][n*64+d]+upos[n*64+d]) * K[b][j][n*64+d]
__global__ void ac_kernel(const float* __restrict__ upos)
{
    const int j0 = blockIdx.x * 64;
    const int b  = blockIdx.y >> 2;
    const int i0 = (blockIdx.y & 3) * 64;
    const int n  = blockIdx.z;
    nt64_body(g_Q + (b * 256 + i0) * 512 + n * 64, upos + n * 64,
              g_K + (b * 256 + j0) * 512 + n * 64,
              g_AC + ((b * 256 + i0) * 8 + n) * 256 + j0, 2048);
}

// ---------------- attn: scores + softmax -> P ----------------
// per block m: S[n][j] = AC[m][n][j] + sum_h rpe[m,j,h]*T[m,n,h], scaled+masked,
// softmax over j, write P.  chunk = 16 j; 2 CTAs/SM.
// lane mapping in compute: jp = lane&7 (j-pair), hs = lane>>3 (h interleave slice);
// lane covers h = w*64 + hs*4 + f*16 + [0,4), f=0..3  (16 h total), 2 j, all 8 n.
// dyn smem floats: rpe_s 2*16*516 | T_s 8*512 | red 8*136 | ss 8*260
#define CHUNK      16
#define RPE_STRIDE 516
#define RPE_BUF    (CHUNK * RPE_STRIDE)    // 8256
#define OFF_T      (2 * RPE_BUF)           // 16512
#define OFF_RED    (OFF_T + 4096)          // 20608
#define OFF_SS     (OFF_RED + 1088)        // 21696
#define ATTN_SMEM  ((OFF_SS + 2080) * 4)   // 95104 bytes

__device__ __forceinline__ void attn_load_chunk(float* dst, const float* src, int tid)
{
    // 16 rows x 512 floats = 2048 float4; 256 threads x 8 float4
    const int jj = tid >> 4;       // 0..15
    const int f0 = tid & 15;       // 0..15
    const float4* g = (const float4*)src + (size_t)jj * 128;
    uint32_t s = (uint32_t)__cvta_generic_to_shared(dst + jj * RPE_STRIDE);
    #pragma unroll
    for (int t = 0; t < 8; t++)
        cpasync16(s + (f0 + t * 16) * 16, g + f0 + t * 16);
}

__global__ __launch_bounds__(256, 2)
void attn_kernel(const float* __restrict__ rpe,
                 const int* __restrict__ seq_len,
                 const int* __restrict__ lex_num)
{
    extern __shared__ __align__(16) float smem[];
    float* rpe_s = smem;
    float* T_s   = smem + OFF_T;
    float* red   = smem + OFF_RED;
    float* ss    = smem + OFF_SS;
    __shared__ int s_limit;

    const int tid  = threadIdx.x;
    const int m    = blockIdx.x;
    const int b    = m >> 8;
    const int w    = tid >> 5;      // warp: h-window (compute) / head (softmax)
    const int lane = tid & 31;

    const float* rpe_m = rpe + (size_t)m * 256 * 512;

    // prefetch chunk 0 ASAP
    attn_load_chunk(rpe_s, rpe_m, tid);
    cpasync_commit();

    // T rows for this m
    {
        const float4* src = (const float4*)(g_T + (size_t)m * 4096);
        float4* dst = (float4*)T_s;
        #pragma unroll
        for (int t = 0; t < 4; t++)
            dst[tid + 256 * t] = src[tid + 256 * t];
    }
    if (tid == 0) s_limit = seq_len[b] + lex_num[0];
    __syncthreads();
    const int limit = s_limit;

    const int jp = lane & 7;        // j-pair index 0..7
    const int hs = lane >> 3;       // h slice 0..3

    for (int c = 0; c < 16; c++) {
        const int j0 = c * CHUNK;
        if (c < 15) {
            attn_load_chunk(rpe_s + ((c + 1) & 1) * RPE_BUF,
                            rpe_m + (size_t)(j0 + CHUNK) * 512, tid);
            cpasync_commit();
            cpasync_wait<1>();
        } else {
            cpasync_wait<0>();
        }
        __syncthreads();

        // compute: lane covers 2 j (jp*2, jp*2+1), 16 h (4 interleaved float4), 8 n
        {
            const float* rbase = rpe_s + ((c & 1) * RPE_BUF)
                               + (jp * 2) * RPE_STRIDE + w * 64 + hs * 4;
            const float* tbase = T_s + w * 64 + hs * 4;
            unsigned long long acc[8][2] = {};
            #pragma unroll
            for (int f = 0; f < 4; f++) {
                ulonglong2 r0 = *(const ulonglong2*)(rbase + f * 16);
                ulonglong2 r1 = *(const ulonglong2*)(rbase + RPE_STRIDE + f * 16);
                #pragma unroll
                for (int n = 0; n < 8; n++) {
                    ulonglong2 t = *(const ulonglong2*)(tbase + n * 512 + f * 16);
                    acc[n][0] = ffma2(r0.x, t.x, acc[n][0]);
                    acc[n][0] = ffma2(r0.y, t.y, acc[n][0]);
                    acc[n][1] = ffma2(r1.x, t.x, acc[n][1]);
                    acc[n][1] = ffma2(r1.y, t.y, acc[n][1]);
                }
            }
            // reduce over the 4 h-slices (lanes stride 8), then store warp partial
            #pragma unroll
            for (int n = 0; n < 8; n++) {
                #pragma unroll
                for (int j2 = 0; j2 < 2; j2++) {
                    float2 fv = unpack2(acc[n][j2]);
                    float v = fv.x + fv.y;
                    v += __shfl_xor_sync(0xffffffffu, v, 8);
                    v += __shfl_xor_sync(0xffffffffu, v, 16);
                    if (hs == 0) red[w * 136 + n * 17 + jp * 2 + j2] = v;
                }
            }
        }
        __syncthreads();

        // reduce over 8 warps, add AC, scale+mask (128 threads)
        if (tid < 128) {
            const int n2 = tid >> 4;
            const int jr = tid & 15;
            float v = 0.f;
            #pragma unroll
            for (int p = 0; p < 8; p++)
                v += red[p * 136 + n2 * 17 + jr];
            v += g_AC[((size_t)m * 8 + n2) * 256 + j0 + jr];
            ss[n2 * 260 + j0 + jr] = (j0 + jr < limit) ? v * 0.125f : -1e15f;
        }
        __syncthreads();
    }

    // softmax: warp w = head w
    {
        float vals[8];
        #pragma unroll
        for (int t = 0; t < 8; t++) vals[t] = ss[w * 260 + lane + 32 * t];
        float mx = vals[0];
        #pragma unroll
        for (int t = 1; t < 8; t++) mx = fmaxf(mx, vals[t]);
        #pragma unroll
        for (int o = 16; o; o >>= 1) mx = fmaxf(mx, __shfl_xor_sync(0xffffffffu, mx, o));
        float sum = 0.f;
        #pragma unroll
        for (int t = 0; t < 8; t++) { vals[t] = __expf(vals[t] - mx); sum += vals[t]; }
        #pragma unroll
        for (int o = 16; o; o >>= 1) sum += __shfl_xor_sync(0xffffffffu, sum, o);
        float inv = 1.f / sum;
        #pragma unroll
        for (int t = 0; t < 8; t++) ss[w * 260 + lane + 32 * t] = vals[t] * inv;
    }
    __syncthreads();

    // write P
    {
        float4* P4 = (float4*)g_P + (size_t)m * 512;
        #pragma unroll
        for (int t = 0; t < 2; t++) {
            int f = tid + 256 * t;          // float4 index, 0..511
            int n = f >> 6;
            int c4 = f & 63;
            P4[f] = *(const float4*)&ss[n * 260 + c4 * 4];
        }
    }
}

// ---------------- ctx: CTX[m][n*64+d] = sum_j P[m][n][j] * V[b][j][n*64+d] ----------------
// 32-i tiles: grid (8, 8, 2) = 128 blocks.
__global__ void ctx_kernel()
{
    __shared__ __align__(16) float Ps[64][34];   // [j][i] transposed, 64 j x 32 i
    __shared__ __align__(16) float Vs[64][68];   // [j][d]

    const int tid = threadIdx.x;
    const int tx = tid & 15, ty = tid >> 4;
    const int i0 = blockIdx.x * 32;
    const int n  = blockIdx.y;
    const int b  = blockIdx.z;

    unsigned long long acc[2][2] = {};

    for (int j0 = 0; j0 < 256; j0 += 64) {
        // P tile: 32 i-rows x 64 j, transposed store
        {
            const int li = tid >> 3;               // i within tile, 0..31
            #pragma unroll
            for (int q = 0; q < 2; q++) {
                int jf = (tid & 7) + q * 8;        // float4 index 0..15 within row
                float4 p4 = *(const float4*)&g_P[(((size_t)(b * 256 + i0 + li)) * 8 + n) * 256 + j0 + jf * 4];
                Ps[jf * 4 + 0][li] = p4.x;
                Ps[jf * 4 + 1][li] = p4.y;
                Ps[jf * 4 + 2][li] = p4.z;
                Ps[jf * 4 + 3][li] = p4.w;
            }
        }
        // V tile: 64 j-rows x 64 d
        {
            const int lj = tid >> 2;
            const int fl = tid & 3;
            #pragma unroll
            for (int q = 0; q < 4; q++) {
                int f4 = fl + q * 4;
                float4 v4 = *(const float4*)&g_V[(size_t)(b * 256 + j0 + lj) * 512 + n * 64 + f4 * 4];
                *(float4*)&Vs[lj][f4 * 4] = v4;
            }
        }
        __syncthreads();

        #pragma unroll 16
        for (int j = 0; j < 64; j++) {
            float2 av = *(const float2*)&Ps[j][ty * 2];
            ulonglong2 bp = *(const ulonglong2*)&Vs[j][tx * 4];
            unsigned long long s0 = splat2(av.x);
            unsigned long long s1 = splat2(av.y);
            acc[0][0] = ffma2(s0, bp.x, acc[0][0]); acc[0][1] = ffma2(s0, bp.y, acc[0][1]);
            acc[1][0] = ffma2(s1, bp.x, acc[1][0]); acc[1][1] = ffma2(s1, bp.y, acc[1][1]);
        }
        __syncthreads();
    }

    #pragma unroll
    for (int r = 0; r < 2; r++) {
        float2 p0 = unpack2(acc[r][0]);
        float2 p1 = unpack2(acc[r][1]);
        float4 o; o.x = p0.x; o.y = p0.y; o.z = p1.x; o.w = p1.y;
        *(float4*)&g_CTX[(size_t)(b * 256 + i0 + ty * 2 + r) * 512 + n * 64 + tx * 4] = o;
    }
}

// ---------------- launch ----------------
extern "C" void kernel_launch(void* const* d_in, const int* in_sizes, int n_in,
                              void* d_out, int out_size)
{
    const float* key     = (const float*)d_in[0];
    const float* query   = (const float*)d_in[1];
    const float* value   = (const float*)d_in[2];
    const int*   seq_len = (const int*)  d_in[3];
    const int*   lex_num = (const int*)  d_in[4];
    const float* rpe     = (const float*)d_in[7];
    const float* Wk      = (const float*)d_in[8];
    const float* bk      = (const float*)d_in[9];
    const float* Wq      = (const float*)d_in[10];
    const float* bq      = (const float*)d_in[11];
    const float* Wv      = (const float*)d_in[12];
    const float* bv      = (const float*)d_in[13];
    const float* Wr      = (const float*)d_in[14];
    const float* upos    = (const float*)d_in[16];
    const float* vpos    = (const float*)d_in[17];
    const float* Wf      = (const float*)d_in[18];
    const float* bf      = (const float*)d_in[19];
    float* out = (float*)d_out;

    static bool attr_set = false;
    if (!attr_set) {
        cudaFuncSetAttribute(attn_kernel,
                             cudaFuncAttributeMaxDynamicSharedMemorySize, ATTN_SMEM);
        attr_set = true;
    }

    proj_kernel <<<dim3(8, 16, 3), 256>>>(key, query, value, Wk, bk, Wq, bq, Wv, bv);
    tilde_kernel<<<dim3(8, 8, 8), 256>>>(Wr, vpos);
    ac_kernel   <<<dim3(4, 8, 8), 256>>>(upos);
    attn_kernel <<<dim3(BB * LL), 256, ATTN_SMEM>>>(rpe, seq_len, lex_num);
    ctx_kernel  <<<dim3(8, 8, 2), 256>>>();
    final_kernel<<<dim3(8, 16), 256>>>(Wf, bf, out);
}

// round 8
// speedup vs baseline: 1.1456x; 1.1456x over previous
#include <cuda_runtime.h>
#include <cstdint>

#define BB 2
#define LL 256
#define HH 512
#define NHH 8
#define DHH 64

// ---------------- scratch (device globals; no allocation) ----------------
__device__ __align__(16) float g_K[BB*LL*HH];
__device__ __align__(16) float g_Q[BB*LL*HH];
__device__ __align__(16) float g_V[BB*LL*HH];
__device__ __align__(16) float g_T[BB*LL*NHH*HH];    // [m][n][h]  8 MB
__device__ __align__(16) float g_AC[BB*LL*NHH*LL];   // [m][n][j]  4 MB
__device__ __align__(16) float g_P[BB*LL*NHH*LL];    // [m][n][j]  4 MB
__device__ __align__(16) float g_CTX[BB*LL*HH];

// ---------------- f32x2 helpers ----------------
__device__ __forceinline__ unsigned long long ffma2(unsigned long long a,
                                                    unsigned long long b,
                                                    unsigned long long c) {
    unsigned long long d;
    asm("fma.rn.f32x2 %0, %1, %2, %3;" : "=l"(d) : "l"(a), "l"(b), "l"(c));
    return d;
}
__device__ __forceinline__ unsigned long long splat2(float a) {
    unsigned long long r;
    asm("mov.b64 %0, {%1, %1};" : "=l"(r) : "f"(a));
    return r;
}
__device__ __forceinline__ float2 unpack2(unsigned long long v) {
    float2 f;
    asm("mov.b64 {%0, %1}, %2;" : "=f"(f.x), "=f"(f.y) : "l"(v));
    return f;
}
__device__ __forceinline__ void cpasync16(uint32_t s, const void* g) {
    asm volatile("cp.async.cg.shared.global [%0], [%1], 16;\n" :: "r"(s), "l"(g));
}
__device__ __forceinline__ void cpasync_commit() {
    asm volatile("cp.async.commit_group;\n" ::: "memory");
}
template <int N>
__device__ __forceinline__ void cpasync_wait() {
    asm volatile("cp.async.wait_group %0;\n" :: "n"(N) : "memory");
}

// ---------------- 32x64-tile GEMM body: C[512,512] = A @ W + bias ----------------
__device__ __forceinline__ void gemm32x64_body(const float* __restrict__ A,
                                               const float* __restrict__ W,
                                               const float* __restrict__ bias,
                                               float* __restrict__ C)
{
    __shared__ __align__(16) float As[32][34];   // [k][m]
    __shared__ __align__(16) float Bs[32][68];   // [k][n]

    const int tid = threadIdx.x;
    const int tx  = tid & 15;
    const int ty  = tid >> 4;
    const int row0 = blockIdx.y * 32;
    const int col0 = blockIdx.x * 64;

    const int lm = tid >> 3;
    const int lk = (tid & 7) * 4;
    const int wr = tid >> 4;
    const int wc = (tid & 15) * 4;

    float4 a0 = *(const float4*)&A[(row0 + lm) * 512 + lk];
    float4 b0 = *(const float4*)&W[(0  + wr) * 512 + col0 + wc];
    float4 b1 = *(const float4*)&W[(16 + wr) * 512 + col0 + wc];

    unsigned long long acc[2][2] = {};

    for (int kt = 0; kt < 512; kt += 32) {
        As[lk + 0][lm] = a0.x; As[lk + 1][lm] = a0.y;
        As[lk + 2][lm] = a0.z; As[lk + 3][lm] = a0.w;
        *(float4*)&Bs[wr][wc]      = b0;
        *(float4*)&Bs[wr + 16][wc] = b1;
        __syncthreads();

        if (kt + 32 < 512) {
            a0 = *(const float4*)&A[(row0 + lm) * 512 + kt + 32 + lk];
            b0 = *(const float4*)&W[(kt + 32 + wr) * 512 + col0 + wc];
            b1 = *(const float4*)&W[(kt + 48 + wr) * 512 + col0 + wc];
        }

        #pragma unroll
        for (int kk = 0; kk < 32; kk++) {
            float2 av = *(const float2*)&As[kk][ty * 2];
            ulonglong2 bp = *(const ulonglong2*)&Bs[kk][tx * 4];
            unsigned long long s0 = splat2(av.x);
            unsigned long long s1 = splat2(av.y);
            acc[0][0] = ffma2(s0, bp.x, acc[0][0]); acc[0][1] = ffma2(s0, bp.y, acc[0][1]);
            acc[1][0] = ffma2(s1, bp.x, acc[1][0]); acc[1][1] = ffma2(s1, bp.y, acc[1][1]);
        }
        __syncthreads();
    }

    float4 bb = *(const float4*)&bias[col0 + tx * 4];
    #pragma unroll
    for (int r = 0; r < 2; r++) {
        float2 p0 = unpack2(acc[r][0]);
        float2 p1 = unpack2(acc[r][1]);
        float4 o;
        o.x = p0.x + bb.x; o.y = p0.y + bb.y;
        o.z = p1.x + bb.z; o.w = p1.y + bb.w;
        *(float4*)&C[(row0 + ty * 2 + r) * 512 + col0 + tx * 4] = o;
    }
}

__global__ void proj_kernel(const float* __restrict__ key,
                            const float* __restrict__ query,
                            const float* __restrict__ value,
                            const float* __restrict__ Wk, const float* __restrict__ bk,
                            const float* __restrict__ Wq, const float* __restrict__ bq,
                            const float* __restrict__ Wv, const float* __restrict__ bv)
{
    const float *A, *W, *bias;
    float* C;
    if (blockIdx.z == 0)      { A = key;   W = Wk; bias = bk; C = g_K; }
    else if (blockIdx.z == 1) { A = query; W = Wq; bias = bq; C = g_Q; }
    else                      { A = value; W = Wv; bias = bv; C = g_V; }
    gemm32x64_body(A, W, bias, C);
}

__global__ void final_kernel(const float* __restrict__ Wf,
                             const float* __restrict__ bf,
                             float* __restrict__ out)
{
    gemm32x64_body(g_CTX, Wf, bf, out);
}

// ---------------- K=64 A@B^T body (tilde + AC) ----------------
__device__ __forceinline__ void nt64_body(const float* __restrict__ Arow0,
                                          const float* __restrict__ avec,
                                          const float* __restrict__ Brow0,
                                          float* __restrict__ Cbase, int ldc)
{
    __shared__ __align__(16) float As[16][68];
    __shared__ __align__(16) float Bs[16][68];

    const int tid = threadIdx.x;
    const int tx = tid & 15, ty = tid >> 4;
    const int lm = tid >> 2;
    const int lk = (tid & 3) * 4;

    unsigned long long acc[4][2] = {};

    for (int kt = 0; kt < 64; kt += 16) {
        float4 a4 = *(const float4*)&Arow0[lm * 512 + kt + lk];
        float4 vb = *(const float4*)&avec[kt + lk];
        a4.x += vb.x; a4.y += vb.y; a4.z += vb.z; a4.w += vb.w;
        As[lk + 0][lm] = a4.x; As[lk + 1][lm] = a4.y;
        As[lk + 2][lm] = a4.z; As[lk + 3][lm] = a4.w;
        float4 b4 = *(const float4*)&Brow0[lm * 512 + kt + lk];
        Bs[lk + 0][lm] = b4.x; Bs[lk + 1][lm] = b4.y;
        Bs[lk + 2][lm] = b4.z; Bs[lk + 3][lm] = b4.w;
        __syncthreads();

        #pragma unroll
        for (int kk = 0; kk < 16; kk++) {
            float4 av = *(const float4*)&As[kk][ty * 4];
            ulonglong2 bp = *(const ulonglong2*)&Bs[kk][tx * 4];
            unsigned long long s0 = splat2(av.x);
            unsigned long long s1 = splat2(av.y);
            unsigned long long s2 = splat2(av.z);
            unsigned long long s3 = splat2(av.w);
            acc[0][0] = ffma2(s0, bp.x, acc[0][0]); acc[0][1] = ffma2(s0, bp.y, acc[0][1]);
            acc[1][0] = ffma2(s1, bp.x, acc[1][0]); acc[1][1] = ffma2(s1, bp.y, acc[1][1]);
            acc[2][0] = ffma2(s2, bp.x, acc[2][0]); acc[2][1] = ffma2(s2, bp.y, acc[2][1]);
            acc[3][0] = ffma2(s3, bp.x, acc[3][0]); acc[3][1] = ffma2(s3, bp.y, acc[3][1]);
        }
        __syncthreads();
    }

    #pragma unroll
    for (int r = 0; r < 4; r++) {
        float2 p0 = unpack2(acc[r][0]);
        float2 p1 = unpack2(acc[r][1]);
        float4 o; o.x = p0.x; o.y = p0.y; o.z = p1.x; o.w = p1.y;
        *(float4*)&Cbase[(ty * 4 + r) * ldc + tx * 4] = o;
    }
}

// tilde (bid<512): T[m][n][h] = sum_d (Q[m][n*64+d]+vpos[n*64+d]) * Wr[h][n*64+d]
// ac (bid>=512):   AC[m][n][j] = sum_d (Q[m][n*64+d]+upos[n*64+d]) * K[b][j][n*64+d]
__global__ void tac_kernel(const float* __restrict__ Wr,
                           const float* __restrict__ vpos,
                           const float* __restrict__ upos)
{
    const int bid = blockIdx.x;
    if (bid < 512) {
        const int n    = bid >> 6;
        const int rest = bid & 63;
        const int h0   = (rest & 7) * 64;
        const int m0   = (rest >> 3) * 64;
        nt64_body(g_Q + m0 * 512 + n * 64, vpos + n * 64,
                  Wr + h0 * 512 + n * 64,
                  g_T + (m0 * 8 + n) * 512 + h0, 4096);
    } else {
        const int r    = bid - 512;
        const int n    = r >> 5;
        const int rest = r & 31;
        const int j0   = (rest & 3) * 64;
        const int q    = rest >> 2;          // 0..7
        const int b    = q >> 2;
        const int i0   = (q & 3) * 64;
        nt64_body(g_Q + (b * 256 + i0) * 512 + n * 64, upos + n * 64,
                  g_K + (b * 256 + j0) * 512 + n * 64,
                  g_AC + ((b * 256 + i0) * 8 + n) * 256 + j0, 2048);
    }
}

// ---------------- attn: warp-autonomous scores + softmax -> P ----------------
// CTA per m=(b,i). Warp w owns j in [w*32, w*32+32), processed in 8 groups of 4 j.
// Per-warp cp.async double buffer, no block barriers in the mainloop.
// Lane covers h float4 indices {lane + 32t, t=0..3} for all 8 n and 4 j;
// merged butterfly (31 shfl) leaves lane L with score (n=L>>2, jj=L&3).
#define JG        4
#define WBUF      (2 * JG * 512)            // 4096 floats per warp
#define OFF_T     (8 * WBUF)                // 32768
#define OFF_SS    (OFF_T + 4096)            // 36864
#define ATTN_SMEM ((OFF_SS + 2080 + 16) * 4)  // ~155.8 KB

__device__ __forceinline__ void attn_issue_group(float* mybuf, const float* rowsrc,
                                                 int lane, int g)
{
    // 4 rows x 512 floats; thread: row = lane>>3, 16B chunks (lane&7) + 8t
    float* dst = mybuf + (g & 1) * (JG * 512);
    const int r  = lane >> 3;
    const int c0 = lane & 7;
    const char* src = (const char*)(rowsrc + r * 512);
    uint32_t s = (uint32_t)__cvta_generic_to_shared(dst + r * 512);
    #pragma unroll
    for (int t = 0; t < 16; t++)
        cpasync16(s + (c0 + t * 8) * 16, src + (c0 + t * 8) * 16);
    cpasync_commit();
}

__global__ __launch_bounds__(256, 1)
void attn_kernel(const float* __restrict__ rpe,
                 const int* __restrict__ seq_len,
                 const int* __restrict__ lex_num)
{
    extern __shared__ __align__(16) float smem[];
    float* T_s = smem + OFF_T;
    float* ss  = smem + OFF_SS;
    __shared__ int s_limit;

    const int tid  = threadIdx.x;
    const int m    = blockIdx.x;
    const int b    = m >> 8;
    const int w    = tid >> 5;
    const int lane = tid & 31;
    const int jw   = w * 32;

    const float* rpe_m = rpe + (size_t)m * 256 * 512;
    float* mybuf = smem + w * WBUF;

    // prefetch groups 0 and 1
    attn_issue_group(mybuf, rpe_m + (size_t)(jw + 0 * JG) * 512, lane, 0);
    attn_issue_group(mybuf, rpe_m + (size_t)(jw + 1 * JG) * 512, lane, 1);

    // T rows for this m
    {
        const float4* src = (const float4*)(g_T + (size_t)m * 4096);
        float4* dst = (float4*)T_s;
        #pragma unroll
        for (int t = 0; t < 4; t++)
            dst[tid + 256 * t] = src[tid + 256 * t];
    }
    if (tid == 0) s_limit = seq_len[b] + lex_num[0];
    __syncthreads();

    // ---- mainloop: no block barriers ----
    for (int g = 0; g < 8; g++) {
        // group-ledger: groups pending before wait = {g} ∪ ({g+1} if issued).
        // For g<7 one younger group is in flight -> wait<1>; at g==7 nothing
        // younger exists, so wait<0> (this was the R7 race).
        if (g < 7) cpasync_wait<1>(); else cpasync_wait<0>();
        __syncwarp();

        const float* rb = mybuf + (g & 1) * (JG * 512);
        unsigned long long acc[32] = {};
        #pragma unroll
        for (int t = 0; t < 4; t++) {
            const int f4 = (lane + t * 32) * 4;    // float offset of this slice
            ulonglong2 rj[JG];
            #pragma unroll
            for (int jj = 0; jj < JG; jj++)
                rj[jj] = *(const ulonglong2*)(rb + jj * 512 + f4);
            #pragma unroll
            for (int n = 0; n < 8; n++) {
                ulonglong2 tv = *(const ulonglong2*)(T_s + n * 512 + f4);
                #pragma unroll
                for (int jj = 0; jj < JG; jj++) {
                    acc[n * 4 + jj] = ffma2(rj[jj].x, tv.x, acc[n * 4 + jj]);
                    acc[n * 4 + jj] = ffma2(rj[jj].y, tv.y, acc[n * 4 + jj]);
                }
            }
        }

        // issue group g+2 (overlaps DRAM with the shuffle tree below)
        if (g + 2 < 8)
            attn_issue_group(mybuf, rpe_m + (size_t)(jw + (g + 2) * JG) * 512, lane, g + 2);

        // collapse f32x2 -> scalar
        float v[32];
        #pragma unroll
        for (int i = 0; i < 32; i++) {
            float2 f2 = unpack2(acc[i]);
            v[i] = f2.x + f2.y;
        }
        // merged butterfly tree: after all stages, lane L owns index L
        #pragma unroll
        for (int s = 16; s >= 1; s >>= 1) {
            #pragma unroll
            for (int i = 0; i < 16; i++) {
                if (i < s) {
                    float send = (lane & s) ? v[i] : v[i + s];
                    float keep = (lane & s) ? v[i + s] : v[i];
                    v[i] = keep + __shfl_xor_sync(0xffffffffu, send, s);
                }
            }
        }
        // lane L: n = L>>2, jj = L&3
        ss[(lane >> 2) * 260 + jw + g * JG + (lane & 3)] = v[0];
    }

    __syncthreads();

    // softmax: warp w = head w; add AC, scale, mask here
    const int limit = s_limit;
    {
        float vals[8];
        #pragma unroll
        for (int t = 0; t < 8; t++) {
            int j = lane + 32 * t;
            float raw = ss[w * 260 + j];
            float ac  = g_AC[((size_t)m * 8 + w) * 256 + j];
            vals[t] = (j < limit) ? (raw + ac) * 0.125f : -1e15f;
        }
        float mx = vals[0];
        #pragma unroll
        for (int t = 1; t < 8; t++) mx = fmaxf(mx, vals[t]);
        #pragma unroll
        for (int o = 16; o; o >>= 1) mx = fmaxf(mx, __shfl_xor_sync(0xffffffffu, mx, o));
        float sum = 0.f;
        #pragma unroll
        for (int t = 0; t < 8; t++) { vals[t] = __expf(vals[t] - mx); sum += vals[t]; }
        #pragma unroll
        for (int o = 16; o; o >>= 1) sum += __shfl_xor_sync(0xffffffffu, sum, o);
        float inv = 1.f / sum;
        #pragma unroll
        for (int t = 0; t < 8; t++) ss[w * 260 + lane + 32 * t] = vals[t] * inv;
    }
    __syncthreads();

    // write P
    {
        float4* P4 = (float4*)g_P + (size_t)m * 512;
        #pragma unroll
        for (int t = 0; t < 2; t++) {
            int f = tid + 256 * t;
            int n = f >> 6;
            int c4 = f & 63;
            P4[f] = *(const float4*)&ss[n * 260 + c4 * 4];
        }
    }
}

// ---------------- ctx: CTX[m][n*64+d] = sum_j P[m][n][j] * V[b][j][n*64+d] ----------------
__global__ void ctx_kernel()
{
    __shared__ __align__(16) float Ps[64][34];
    __shared__ __align__(16) float Vs[64][68];

    const int tid = threadIdx.x;
    const int tx = tid & 15, ty = tid >> 4;
    const int i0 = blockIdx.x * 32;
    const int n  = blockIdx.y;
    const int b  = blockIdx.z;

    unsigned long long acc[2][2] = {};

    for (int j0 = 0; j0 < 256; j0 += 64) {
        {
            const int li = tid >> 3;
            #pragma unroll
            for (int q = 0; q < 2; q++) {
                int jf = (tid & 7) + q * 8;
                float4 p4 = *(const float4*)&g_P[(((size_t)(b * 256 + i0 + li)) * 8 + n) * 256 + j0 + jf * 4];
                Ps[jf * 4 + 0][li] = p4.x;
                Ps[jf * 4 + 1][li] = p4.y;
                Ps[jf * 4 + 2][li] = p4.z;
                Ps[jf * 4 + 3][li] = p4.w;
            }
        }
        {
            const int lj = tid >> 2;
            const int fl = tid & 3;
            #pragma unroll
            for (int q = 0; q < 4; q++) {
                int f4 = fl + q * 4;
                float4 v4 = *(const float4*)&g_V[(size_t)(b * 256 + j0 + lj) * 512 + n * 64 + f4 * 4];
                *(float4*)&Vs[lj][f4 * 4] = v4;
            }
        }
        __syncthreads();

        #pragma unroll 16
        for (int j = 0; j < 64; j++) {
            float2 av = *(const float2*)&Ps[j][ty * 2];
            ulonglong2 bp = *(const ulonglong2*)&Vs[j][tx * 4];
            unsigned long long s0 = splat2(av.x);
            unsigned long long s1 = splat2(av.y);
            acc[0][0] = ffma2(s0, bp.x, acc[0][0]); acc[0][1] = ffma2(s0, bp.y, acc[0][1]);
            acc[1][0] = ffma2(s1, bp.x, acc[1][0]); acc[1][1] = ffma2(s1, bp.y, acc[1][1]);
        }
        __syncthreads();
    }

    #pragma unroll
    for (int r = 0; r < 2; r++) {
        float2 p0 = unpack2(acc[r][0]);
        float2 p1 = unpack2(acc[r][1]);
        float4 o; o.x = p0.x; o.y = p0.y; o.z = p1.x; o.w = p1.y;
        *(float4*)&g_CTX[(size_t)(b * 256 + i0 + ty * 2 + r) * 512 + n * 64 + tx * 4] = o;
    }
}

// ---------------- launch ----------------
extern "C" void kernel_launch(void* const* d_in, const int* in_sizes, int n_in,
                              void* d_out, int out_size)
{
    const float* key     = (const float*)d_in[0];
    const float* query   = (const float*)d_in[1];
    const float* value   = (const float*)d_in[2];
    const int*   seq_len = (const int*)  d_in[3];
    const int*   lex_num = (const int*)  d_in[4];
    const float* rpe     = (const float*)d_in[7];
    const float* Wk      = (const float*)d_in[8];
    const float* bk      = (const float*)d_in[9];
    const float* Wq      = (const float*)d_in[10];
    const float* bq      = (const float*)d_in[11];
    const float* Wv      = (const float*)d_in[12];
    const float* bv      = (const float*)d_in[13];
    const float* Wr      = (const float*)d_in[14];
    const float* upos    = (const float*)d_in[16];
    const float* vpos    = (const float*)d_in[17];
    const float* Wf      = (const float*)d_in[18];
    const float* bf      = (const float*)d_in[19];
    float* out = (float*)d_out;

    static bool attr_set = false;
    if (!attr_set) {
        cudaFuncSetAttribute(attn_kernel,
                             cudaFuncAttributeMaxDynamicSharedMemorySize, ATTN_SMEM);
        attr_set = true;
    }

    proj_kernel <<<dim3(8, 16, 3), 256>>>(key, query, value, Wk, bk, Wq, bq, Wv, bv);
    tac_kernel  <<<dim3(768), 256>>>(Wr, vpos, upos);
    attn_kernel <<<dim3(BB * LL), 256, ATTN_SMEM>>>(rpe, seq_len, lex_num);
    ctx_kernel  <<<dim3(8, 8, 2), 256>>>();
    final_kernel<<<dim3(8, 16), 256>>>(Wf, bf, out);
}

// round 9
// speedup vs baseline: 1.2234x; 1.0679x over previous
#include <cuda_runtime.h>
#include <cstdint>

#define BB 2
#define LL 256
#define HH 512
#define NHH 8
#define DHH 64

// ---------------- scratch (device globals; no allocation) ----------------
__device__ __align__(16) float g_K[BB*LL*HH];
__device__ __align__(16) float g_Q[BB*LL*HH];
__device__ __align__(16) float g_V[BB*LL*HH];
__device__ __align__(16) float g_T[BB*LL*NHH*HH];    // [m][n][h]  8 MB
__device__ __align__(16) float g_AC[BB*LL*NHH*LL];   // [m][n][j]  4 MB
__device__ __align__(16) float g_P[BB*LL*NHH*LL];    // [m][n][j]  4 MB
__device__ __align__(16) float g_CTX[BB*LL*HH];

// ---------------- f32x2 helpers ----------------
__device__ __forceinline__ unsigned long long ffma2(unsigned long long a,
                                                    unsigned long long b,
                                                    unsigned long long c) {
    unsigned long long d;
    asm("fma.rn.f32x2 %0, %1, %2, %3;" : "=l"(d) : "l"(a), "l"(b), "l"(c));
    return d;
}
__device__ __forceinline__ unsigned long long splat2(float a) {
    unsigned long long r;
    asm("mov.b64 %0, {%1, %1};" : "=l"(r) : "f"(a));
    return r;
}
__device__ __forceinline__ float2 unpack2(unsigned long long v) {
    float2 f;
    asm("mov.b64 {%0, %1}, %2;" : "=f"(f.x), "=f"(f.y) : "l"(v));
    return f;
}
__device__ __forceinline__ void cpasync16(uint32_t s, const void* g) {
    asm volatile("cp.async.cg.shared.global [%0], [%1], 16;\n" :: "r"(s), "l"(g));
}
__device__ __forceinline__ void cpasync_commit() {
    asm volatile("cp.async.commit_group;\n" ::: "memory");
}
template <int N>
__device__ __forceinline__ void cpasync_wait() {
    asm volatile("cp.async.wait_group %0;\n" :: "n"(N) : "memory");
}

// ---------------- 32x64-tile GEMM, 128 threads, 4x4 microtile ----------------
// C[512,512] = A[512,512] @ W[512,512] + bias.  k-tile 32, reg double-buffer.
__device__ __forceinline__ void gemm32x64_body(const float* __restrict__ A,
                                               const float* __restrict__ W,
                                               const float* __restrict__ bias,
                                               float* __restrict__ C)
{
    __shared__ __align__(16) float As[32][36];   // [k][m]
    __shared__ __align__(16) float Bs[32][68];   // [k][n]

    const int tid = threadIdx.x;        // 0..127
    const int tx  = tid & 15;           // 16 col groups (4 cols each)
    const int ty  = tid >> 4;           // 8 row groups (4 rows each)
    const int row0 = blockIdx.y * 32;
    const int col0 = blockIdx.x * 64;

    const int lm = tid >> 2;            // A row 0..31
    const int lk = (tid & 3) * 8;       // A k offset: 0,8,16,24 (2 float4 each)
    const int brr = tid >> 4;           // B base row 0..7
    const int bc  = (tid & 15) * 4;     // B col offset

    float4 a0 = *(const float4*)&A[(row0 + lm) * 512 + lk];
    float4 a1 = *(const float4*)&A[(row0 + lm) * 512 + lk + 4];
    float4 b0 = *(const float4*)&W[(brr +  0) * 512 + col0 + bc];
    float4 b1 = *(const float4*)&W[(brr +  8) * 512 + col0 + bc];
    float4 b2 = *(const float4*)&W[(brr + 16) * 512 + col0 + bc];
    float4 b3 = *(const float4*)&W[(brr + 24) * 512 + col0 + bc];

    unsigned long long acc[4][2] = {};

    for (int kt = 0; kt < 512; kt += 32) {
        As[lk + 0][lm] = a0.x; As[lk + 1][lm] = a0.y;
        As[lk + 2][lm] = a0.z; As[lk + 3][lm] = a0.w;
        As[lk + 4][lm] = a1.x; As[lk + 5][lm] = a1.y;
        As[lk + 6][lm] = a1.z; As[lk + 7][lm] = a1.w;
        *(float4*)&Bs[brr +  0][bc] = b0;
        *(float4*)&Bs[brr +  8][bc] = b1;
        *(float4*)&Bs[brr + 16][bc] = b2;
        *(float4*)&Bs[brr + 24][bc] = b3;
        __syncthreads();

        if (kt + 32 < 512) {
            a0 = *(const float4*)&A[(row0 + lm) * 512 + kt + 32 + lk];
            a1 = *(const float4*)&A[(row0 + lm) * 512 + kt + 32 + lk + 4];
            b0 = *(const float4*)&W[(kt + 32 + brr +  0) * 512 + col0 + bc];
            b1 = *(const float4*)&W[(kt + 32 + brr +  8) * 512 + col0 + bc];
            b2 = *(const float4*)&W[(kt + 32 + brr + 16) * 512 + col0 + bc];
            b3 = *(const float4*)&W[(kt + 32 + brr + 24) * 512 + col0 + bc];
        }

        #pragma unroll
        for (int kk = 0; kk < 32; kk++) {
            float4 av = *(const float4*)&As[kk][ty * 4];
            ulonglong2 bp = *(const ulonglong2*)&Bs[kk][tx * 4];
            unsigned long long s0 = splat2(av.x);
            unsigned long long s1 = splat2(av.y);
            unsigned long long s2 = splat2(av.z);
            unsigned long long s3 = splat2(av.w);
            acc[0][0] = ffma2(s0, bp.x, acc[0][0]); acc[0][1] = ffma2(s0, bp.y, acc[0][1]);
            acc[1][0] = ffma2(s1, bp.x, acc[1][0]); acc[1][1] = ffma2(s1, bp.y, acc[1][1]);
            acc[2][0] = ffma2(s2, bp.x, acc[2][0]); acc[2][1] = ffma2(s2, bp.y, acc[2][1]);
            acc[3][0] = ffma2(s3, bp.x, acc[3][0]); acc[3][1] = ffma2(s3, bp.y, acc[3][1]);
        }
        __syncthreads();
    }

    float4 bb = *(const float4*)&bias[col0 + tx * 4];
    #pragma unroll
    for (int r = 0; r < 4; r++) {
        float2 p0 = unpack2(acc[r][0]);
        float2 p1 = unpack2(acc[r][1]);
        float4 o;
        o.x = p0.x + bb.x; o.y = p0.y + bb.y;
        o.z = p1.x + bb.z; o.w = p1.y + bb.w;
        *(float4*)&C[(row0 + ty * 4 + r) * 512 + col0 + tx * 4] = o;
    }
}

__global__ void proj_kernel(const float* __restrict__ key,
                            const float* __restrict__ query,
                            const float* __restrict__ value,
                            const float* __restrict__ Wk, const float* __restrict__ bk,
                            const float* __restrict__ Wq, const float* __restrict__ bq,
                            const float* __restrict__ Wv, const float* __restrict__ bv)
{
    const float *A, *W, *bias;
    float* C;
    if (blockIdx.z == 0)      { A = key;   W = Wk; bias = bk; C = g_K; }
    else if (blockIdx.z == 1) { A = query; W = Wq; bias = bq; C = g_Q; }
    else                      { A = value; W = Wv; bias = bv; C = g_V; }
    gemm32x64_body(A, W, bias, C);
}

__global__ void final_kernel(const float* __restrict__ Wf,
                             const float* __restrict__ bf,
                             float* __restrict__ out)
{
    gemm32x64_body(g_CTX, Wf, bf, out);
}

// ---------------- K=64 A@B^T body (tilde + AC) ----------------
__device__ __forceinline__ void nt64_body(const float* __restrict__ Arow0,
                                          const float* __restrict__ avec,
                                          const float* __restrict__ Brow0,
                                          float* __restrict__ Cbase, int ldc)
{
    __shared__ __align__(16) float As[16][68];
    __shared__ __align__(16) float Bs[16][68];

    const int tid = threadIdx.x;
    const int tx = tid & 15, ty = tid >> 4;
    const int lm = tid >> 2;
    const int lk = (tid & 3) * 4;

    unsigned long long acc[4][2] = {};

    for (int kt = 0; kt < 64; kt += 16) {
        float4 a4 = *(const float4*)&Arow0[lm * 512 + kt + lk];
        float4 vb = *(const float4*)&avec[kt + lk];
        a4.x += vb.x; a4.y += vb.y; a4.z += vb.z; a4.w += vb.w;
        As[lk + 0][lm] = a4.x; As[lk + 1][lm] = a4.y;
        As[lk + 2][lm] = a4.z; As[lk + 3][lm] = a4.w;
        float4 b4 = *(const float4*)&Brow0[lm * 512 + kt + lk];
        Bs[lk + 0][lm] = b4.x; Bs[lk + 1][lm] = b4.y;
        Bs[lk + 2][lm] = b4.z; Bs[lk + 3][lm] = b4.w;
        __syncthreads();

        #pragma unroll
        for (int kk = 0; kk < 16; kk++) {
            float4 av = *(const float4*)&As[kk][ty * 4];
            ulonglong2 bp = *(const ulonglong2*)&Bs[kk][tx * 4];
            unsigned long long s0 = splat2(av.x);
            unsigned long long s1 = splat2(av.y);
            unsigned long long s2 = splat2(av.z);
            unsigned long long s3 = splat2(av.w);
            acc[0][0] = ffma2(s0, bp.x, acc[0][0]); acc[0][1] = ffma2(s0, bp.y, acc[0][1]);
            acc[1][0] = ffma2(s1, bp.x, acc[1][0]); acc[1][1] = ffma2(s1, bp.y, acc[1][1]);
            acc[2][0] = ffma2(s2, bp.x, acc[2][0]); acc[2][1] = ffma2(s2, bp.y, acc[2][1]);
            acc[3][0] = ffma2(s3, bp.x, acc[3][0]); acc[3][1] = ffma2(s3, bp.y, acc[3][1]);
        }
        __syncthreads();
    }

    #pragma unroll
    for (int r = 0; r < 4; r++) {
        float2 p0 = unpack2(acc[r][0]);
        float2 p1 = unpack2(acc[r][1]);
        float4 o; o.x = p0.x; o.y = p0.y; o.z = p1.x; o.w = p1.y;
        *(float4*)&Cbase[(ty * 4 + r) * ldc + tx * 4] = o;
    }
}

// tilde (bid<512): T[m][n][h] = sum_d (Q[m][n*64+d]+vpos[n*64+d]) * Wr[h][n*64+d]
// ac (bid>=512):   AC[m][n][j] = sum_d (Q[m][n*64+d]+upos[n*64+d]) * K[b][j][n*64+d]
__global__ void tac_kernel(const float* __restrict__ Wr,
                           const float* __restrict__ vpos,
                           const float* __restrict__ upos)
{
    const int bid = blockIdx.x;
    if (bid < 512) {
        const int n    = bid >> 6;
        const int rest = bid & 63;
        const int h0   = (rest & 7) * 64;
        const int m0   = (rest >> 3) * 64;
        nt64_body(g_Q + m0 * 512 + n * 64, vpos + n * 64,
                  Wr + h0 * 512 + n * 64,
                  g_T + (m0 * 8 + n) * 512 + h0, 4096);
    } else {
        const int r    = bid - 512;
        const int n    = r >> 5;
        const int rest = r & 31;
        const int j0   = (rest & 3) * 64;
        const int q    = rest >> 2;          // 0..7
        const int b    = q >> 2;
        const int i0   = (q & 3) * 64;
        nt64_body(g_Q + (b * 256 + i0) * 512 + n * 64, upos + n * 64,
                  g_K + (b * 256 + j0) * 512 + n * 64,
                  g_AC + ((b * 256 + i0) * 8 + n) * 256 + j0, 2048);
    }
}

// ---------------- attn: warp-autonomous scores + softmax -> P ----------------
// (unchanged from R8 — the working version)
#define JG        4
#define WBUF      (2 * JG * 512)            // 4096 floats per warp
#define OFF_T     (8 * WBUF)                // 32768
#define OFF_SS    (OFF_T + 4096)            // 36864
#define ATTN_SMEM ((OFF_SS + 2080 + 16) * 4)  // ~155.8 KB

__device__ __forceinline__ void attn_issue_group(float* mybuf, const float* rowsrc,
                                                 int lane, int g)
{
    float* dst = mybuf + (g & 1) * (JG * 512);
    const int r  = lane >> 3;
    const int c0 = lane & 7;
    const char* src = (const char*)(rowsrc + r * 512);
    uint32_t s = (uint32_t)__cvta_generic_to_shared(dst + r * 512);
    #pragma unroll
    for (int t = 0; t < 16; t++)
        cpasync16(s + (c0 + t * 8) * 16, src + (c0 + t * 8) * 16);
    cpasync_commit();
}

__global__ __launch_bounds__(256, 1)
void attn_kernel(const float* __restrict__ rpe,
                 const int* __restrict__ seq_len,
                 const int* __restrict__ lex_num)
{
    extern __shared__ __align__(16) float smem[];
    float* T_s = smem + OFF_T;
    float* ss  = smem + OFF_SS;
    __shared__ int s_limit;

    const int tid  = threadIdx.x;
    const int m    = blockIdx.x;
    const int b    = m >> 8;
    const int w    = tid >> 5;
    const int lane = tid & 31;
    const int jw   = w * 32;

    const float* rpe_m = rpe + (size_t)m * 256 * 512;
    float* mybuf = smem + w * WBUF;

    attn_issue_group(mybuf, rpe_m + (size_t)(jw + 0 * JG) * 512, lane, 0);
    attn_issue_group(mybuf, rpe_m + (size_t)(jw + 1 * JG) * 512, lane, 1);

    {
        const float4* src = (const float4*)(g_T + (size_t)m * 4096);
        float4* dst = (float4*)T_s;
        #pragma unroll
        for (int t = 0; t < 4; t++)
            dst[tid + 256 * t] = src[tid + 256 * t];
    }
    if (tid == 0) s_limit = seq_len[b] + lex_num[0];
    __syncthreads();

    for (int g = 0; g < 8; g++) {
        // ledger: g<7 has one younger group in flight -> wait<1>; g==7 -> wait<0>
        if (g < 7) cpasync_wait<1>(); else cpasync_wait<0>();
        __syncwarp();

        const float* rb = mybuf + (g & 1) * (JG * 512);
        unsigned long long acc[32] = {};
        #pragma unroll
        for (int t = 0; t < 4; t++) {
            const int f4 = (lane + t * 32) * 4;
            ulonglong2 rj[JG];
            #pragma unroll
            for (int jj = 0; jj < JG; jj++)
                rj[jj] = *(const ulonglong2*)(rb + jj * 512 + f4);
            #pragma unroll
            for (int n = 0; n < 8; n++) {
                ulonglong2 tv = *(const ulonglong2*)(T_s + n * 512 + f4);
                #pragma unroll
                for (int jj = 0; jj < JG; jj++) {
                    acc[n * 4 + jj] = ffma2(rj[jj].x, tv.x, acc[n * 4 + jj]);
                    acc[n * 4 + jj] = ffma2(rj[jj].y, tv.y, acc[n * 4 + jj]);
                }
            }
        }

        if (g + 2 < 8)
            attn_issue_group(mybuf, rpe_m + (size_t)(jw + (g + 2) * JG) * 512, lane, g + 2);

        float v[32];
        #pragma unroll
        for (int i = 0; i < 32; i++) {
            float2 f2 = unpack2(acc[i]);
            v[i] = f2.x + f2.y;
        }
        #pragma unroll
        for (int s = 16; s >= 1; s >>= 1) {
            #pragma unroll
            for (int i = 0; i < 16; i++) {
                if (i < s) {
                    float send = (lane & s) ? v[i] : v[i + s];
                    float keep = (lane & s) ? v[i + s] : v[i];
                    v[i] = keep + __shfl_xor_sync(0xffffffffu, send, s);
                }
            }
        }
        ss[(lane >> 2) * 260 + jw + g * JG + (lane & 3)] = v[0];
    }

    __syncthreads();

    const int limit = s_limit;
    {
        float vals[8];
        #pragma unroll
        for (int t = 0; t < 8; t++) {
            int j = lane + 32 * t;
            float raw = ss[w * 260 + j];
            float ac  = g_AC[((size_t)m * 8 + w) * 256 + j];
            vals[t] = (j < limit) ? (raw + ac) * 0.125f : -1e15f;
        }
        float mx = vals[0];
        #pragma unroll
        for (int t = 1; t < 8; t++) mx = fmaxf(mx, vals[t]);
        #pragma unroll
        for (int o = 16; o; o >>= 1) mx = fmaxf(mx, __shfl_xor_sync(0xffffffffu, mx, o));
        float sum = 0.f;
        #pragma unroll
        for (int t = 0; t < 8; t++) { vals[t] = __expf(vals[t] - mx); sum += vals[t]; }
        #pragma unroll
        for (int o = 16; o; o >>= 1) sum += __shfl_xor_sync(0xffffffffu, sum, o);
        float inv = 1.f / sum;
        #pragma unroll
        for (int t = 0; t < 8; t++) ss[w * 260 + lane + 32 * t] = vals[t] * inv;
    }
    __syncthreads();

    {
        float4* P4 = (float4*)g_P + (size_t)m * 512;
        #pragma unroll
        for (int t = 0; t < 2; t++) {
            int f = tid + 256 * t;
            int n = f >> 6;
            int c4 = f & 63;
            P4[f] = *(const float4*)&ss[n * 260 + c4 * 4];
        }
    }
}

// ---------------- ctx: CTX[m][n*64+d] = sum_j P[m][n][j] * V[b][j][n*64+d] ----------------
// 16-i tiles: grid (16, 8, 2) = 256 blocks, 256 threads, 1x4 microtile.
__global__ void ctx_kernel()
{
    __shared__ __align__(16) float Ps[64][17];   // [j][i], 16 i
    __shared__ __align__(16) float Vs[64][68];   // [j][d]

    const int tid = threadIdx.x;
    const int tx = tid & 15;        // 16 d-groups (4 each)
    const int ty = tid >> 4;        // 16 i rows (1 each)
    const int i0 = blockIdx.x * 16;
    const int n  = blockIdx.y;
    const int b  = blockIdx.z;

    unsigned long long acc[2] = {};

    for (int j0 = 0; j0 < 256; j0 += 64) {
        // P tile: 16 i-rows x 64 j -> 256 float4, one per thread, transposed store
        {
            const int li = tid >> 4;     // 0..15
            const int jf = tid & 15;     // float4 idx in row
            float4 p4 = *(const float4*)&g_P[(((size_t)(b * 256 + i0 + li)) * 8 + n) * 256 + j0 + jf * 4];
            Ps[jf * 4 + 0][li] = p4.x;
            Ps[jf * 4 + 1][li] = p4.y;
            Ps[jf * 4 + 2][li] = p4.z;
            Ps[jf * 4 + 3][li] = p4.w;
        }
        // V tile: 64 j-rows x 64 d
        {
            const int lj = tid >> 2;
            const int fl = tid & 3;
            #pragma unroll
            for (int q = 0; q < 4; q++) {
                int f4 = fl + q * 4;
                float4 v4 = *(const float4*)&g_V[(size_t)(b * 256 + j0 + lj) * 512 + n * 64 + f4 * 4];
                *(float4*)&Vs[lj][f4 * 4] = v4;
            }
        }
        __syncthreads();

        #pragma unroll 16
        for (int j = 0; j < 64; j++) {
            float a = Ps[j][ty];
            ulonglong2 bp = *(const ulonglong2*)&Vs[j][tx * 4];
            unsigned long long s = splat2(a);
            acc[0] = ffma2(s, bp.x, acc[0]);
            acc[1] = ffma2(s, bp.y, acc[1]);
        }
        __syncthreads();
    }

    {
        float2 p0 = unpack2(acc[0]);
        float2 p1 = unpack2(acc[1]);
        float4 o; o.x = p0.x; o.y = p0.y; o.z = p1.x; o.w = p1.y;
        *(float4*)&g_CTX[(size_t)(b * 256 + i0 + ty) * 512 + n * 64 + tx * 4] = o;
    }
}

// ---------------- launch ----------------
extern "C" void kernel_launch(void* const* d_in, const int* in_sizes, int n_in,
                              void* d_out, int out_size)
{
    const float* key     = (const float*)d_in[0];
    const float* query   = (const float*)d_in[1];
    const float* value   = (const float*)d_in[2];
    const int*   seq_len = (const int*)  d_in[3];
    const int*   lex_num = (const int*)  d_in[4];
    const float* rpe     = (const float*)d_in[7];
    const float* Wk      = (const float*)d_in[8];
    const float* bk      = (const float*)d_in[9];
    const float* Wq      = (const float*)d_in[10];
    const float* bq      = (const float*)d_in[11];
    const float* Wv      = (const float*)d_in[12];
    const float* bv      = (const float*)d_in[13];
    const float* Wr      = (const float*)d_in[14];
    const float* upos    = (const float*)d_in[16];
    const float* vpos    = (const float*)d_in[17];
    const float* Wf      = (const float*)d_in[18];
    const float* bf      = (const float*)d_in[19];
    float* out = (float*)d_out;

    static bool attr_set = false;
    if (!attr_set) {
        cudaFuncSetAttribute(attn_kernel,
                             cudaFuncAttributeMaxDynamicSharedMemorySize, ATTN_SMEM);
        attr_set = true;
    }

    proj_kernel <<<dim3(8, 16, 3), 128>>>(key, query, value, Wk, bk, Wq, bq, Wv, bv);
    tac_kernel  <<<dim3(768), 256>>>(Wr, vpos, upos);
    attn_kernel <<<dim3(BB * LL), 256, ATTN_SMEM>>>(rpe, seq_len, lex_num);
    ctx_kernel  <<<dim3(16, 8, 2), 256>>>();
    final_kernel<<<dim3(8, 16), 128>>>(Wf, bf, out);
}

// round 10
// speedup vs baseline: 1.2918x; 1.0559x over previous
#include <cuda_runtime.h>
#include <cstdint>

#define BB 2
#define LL 256
#define HH 512
#define NHH 8
#define DHH 64

// ---------------- scratch (device globals; no allocation) ----------------
__device__ __align__(16) float g_K[BB*LL*HH];
__device__ __align__(16) float g_Q[BB*LL*HH];
__device__ __align__(16) float g_V[BB*LL*HH];
__device__ __align__(16) float g_T[BB*LL*NHH*HH];    // [m][n][h]  8 MB
__device__ __align__(16) float g_AC[BB*LL*NHH*LL];   // [m][n][j]  4 MB
__device__ __align__(16) float g_P[BB*LL*NHH*LL];    // [m][n][j]  4 MB
__device__ __align__(16) float g_CTX[BB*LL*HH];

// ---------------- f32x2 helpers ----------------
__device__ __forceinline__ unsigned long long ffma2(unsigned long long a,
                                                    unsigned long long b,
                                                    unsigned long long c) {
    unsigned long long d;
    asm("fma.rn.f32x2 %0, %1, %2, %3;" : "=l"(d) : "l"(a), "l"(b), "l"(c));
    return d;
}
__device__ __forceinline__ unsigned long long splat2(float a) {
    unsigned long long r;
    asm("mov.b64 %0, {%1, %1};" : "=l"(r) : "f"(a));
    return r;
}
__device__ __forceinline__ float2 unpack2(unsigned long long v) {
    float2 f;
    asm("mov.b64 {%0, %1}, %2;" : "=f"(f.x), "=f"(f.y) : "l"(v));
    return f;
}
__device__ __forceinline__ void cpasync16(uint32_t s, const void* g) {
    asm volatile("cp.async.cg.shared.global [%0], [%1], 16;\n" :: "r"(s), "l"(g));
}
__device__ __forceinline__ void cpasync_commit() {
    asm volatile("cp.async.commit_group;\n" ::: "memory");
}
template <int N>
__device__ __forceinline__ void cpasync_wait() {
    asm volatile("cp.async.wait_group %0;\n" :: "n"(N) : "memory");
}

// ---------------- 32x64-tile GEMM, 128 threads, 4x4 microtile ----------------
__device__ __forceinline__ void gemm32x64_body(const float* __restrict__ A,
                                               const float* __restrict__ W,
                                               const float* __restrict__ bias,
                                               float* __restrict__ C)
{
    __shared__ __align__(16) float As[32][36];   // [k][m]
    __shared__ __align__(16) float Bs[32][68];   // [k][n]

    const int tid = threadIdx.x;        // 0..127
    const int tx  = tid & 15;
    const int ty  = tid >> 4;
    const int row0 = blockIdx.y * 32;
    const int col0 = blockIdx.x * 64;

    const int lm = tid >> 2;            // A row 0..31
    const int lk = (tid & 3) * 8;       // A k offset
    const int brr = tid >> 4;           // B base row 0..7
    const int bc  = (tid & 15) * 4;     // B col offset

    float4 a0 = *(const float4*)&A[(row0 + lm) * 512 + lk];
    float4 a1 = *(const float4*)&A[(row0 + lm) * 512 + lk + 4];
    float4 b0 = *(const float4*)&W[(brr +  0) * 512 + col0 + bc];
    float4 b1 = *(const float4*)&W[(brr +  8) * 512 + col0 + bc];
    float4 b2 = *(const float4*)&W[(brr + 16) * 512 + col0 + bc];
    float4 b3 = *(const float4*)&W[(brr + 24) * 512 + col0 + bc];

    unsigned long long acc[4][2] = {};

    for (int kt = 0; kt < 512; kt += 32) {
        As[lk + 0][lm] = a0.x; As[lk + 1][lm] = a0.y;
        As[lk + 2][lm] = a0.z; As[lk + 3][lm] = a0.w;
        As[lk + 4][lm] = a1.x; As[lk + 5][lm] = a1.y;
        As[lk + 6][lm] = a1.z; As[lk + 7][lm] = a1.w;
        *(float4*)&Bs[brr +  0][bc] = b0;
        *(float4*)&Bs[brr +  8][bc] = b1;
        *(float4*)&Bs[brr + 16][bc] = b2;
        *(float4*)&Bs[brr + 24][bc] = b3;
        __syncthreads();

        if (kt + 32 < 512) {
            a0 = *(const float4*)&A[(row0 + lm) * 512 + kt + 32 + lk];
            a1 = *(const float4*)&A[(row0 + lm) * 512 + kt + 32 + lk + 4];
            b0 = *(const float4*)&W[(kt + 32 + brr +  0) * 512 + col0 + bc];
            b1 = *(const float4*)&W[(kt + 32 + brr +  8) * 512 + col0 + bc];
            b2 = *(const float4*)&W[(kt + 32 + brr + 16) * 512 + col0 + bc];
            b3 = *(const float4*)&W[(kt + 32 + brr + 24) * 512 + col0 + bc];
        }

        #pragma unroll
        for (int kk = 0; kk < 32; kk++) {
            float4 av = *(const float4*)&As[kk][ty * 4];
            ulonglong2 bp = *(const ulonglong2*)&Bs[kk][tx * 4];
            unsigned long long s0 = splat2(av.x);
            unsigned long long s1 = splat2(av.y);
            unsigned long long s2 = splat2(av.z);
            unsigned long long s3 = splat2(av.w);
            acc[0][0] = ffma2(s0, bp.x, acc[0][0]); acc[0][1] = ffma2(s0, bp.y, acc[0][1]);
            acc[1][0] = ffma2(s1, bp.x, acc[1][0]); acc[1][1] = ffma2(s1, bp.y, acc[1][1]);
            acc[2][0] = ffma2(s2, bp.x, acc[2][0]); acc[2][1] = ffma2(s2, bp.y, acc[2][1]);
            acc[3][0] = ffma2(s3, bp.x, acc[3][0]); acc[3][1] = ffma2(s3, bp.y, acc[3][1]);
        }
        __syncthreads();
    }

    float4 bb = *(const float4*)&bias[col0 + tx * 4];
    #pragma unroll
    for (int r = 0; r < 4; r++) {
        float2 p0 = unpack2(acc[r][0]);
        float2 p1 = unpack2(acc[r][1]);
        float4 o;
        o.x = p0.x + bb.x; o.y = p0.y + bb.y;
        o.z = p1.x + bb.z; o.w = p1.y + bb.w;
        *(float4*)&C[(row0 + ty * 4 + r) * 512 + col0 + tx * 4] = o;
    }
}

__global__ void proj_kernel(const float* __restrict__ key,
                            const float* __restrict__ query,
                            const float* __restrict__ value,
                            const float* __restrict__ Wk, const float* __restrict__ bk,
                            const float* __restrict__ Wq, const float* __restrict__ bq,
                            const float* __restrict__ Wv, const float* __restrict__ bv)
{
    const float *A, *W, *bias;
    float* C;
    if (blockIdx.z == 0)      { A = key;   W = Wk; bias = bk; C = g_K; }
    else if (blockIdx.z == 1) { A = query; W = Wq; bias = bq; C = g_Q; }
    else                      { A = value; W = Wv; bias = bv; C = g_V; }
    gemm32x64_body(A, W, bias, C);
}

__global__ void final_kernel(const float* __restrict__ Wf,
                             const float* __restrict__ bf,
                             float* __restrict__ out)
{
    gemm32x64_body(g_CTX, Wf, bf, out);
}

// ---------------- K=64 A@B^T body (tilde + AC) ----------------
__device__ __forceinline__ void nt64_body(const float* __restrict__ Arow0,
                                          const float* __restrict__ avec,
                                          const float* __restrict__ Brow0,
                                          float* __restrict__ Cbase, int ldc)
{
    __shared__ __align__(16) float As[16][68];
    __shared__ __align__(16) float Bs[16][68];

    const int tid = threadIdx.x;
    const int tx = tid & 15, ty = tid >> 4;
    const int lm = tid >> 2;
    const int lk = (tid & 3) * 4;

    unsigned long long acc[4][2] = {};

    for (int kt = 0; kt < 64; kt += 16) {
        float4 a4 = *(const float4*)&Arow0[lm * 512 + kt + lk];
        float4 vb = *(const float4*)&avec[kt + lk];
        a4.x += vb.x; a4.y += vb.y; a4.z += vb.z; a4.w += vb.w;
        As[lk + 0][lm] = a4.x; As[lk + 1][lm] = a4.y;
        As[lk + 2][lm] = a4.z; As[lk + 3][lm] = a4.w;
        float4 b4 = *(const float4*)&Brow0[lm * 512 + kt + lk];
        Bs[lk + 0][lm] = b4.x; Bs[lk + 1][lm] = b4.y;
        Bs[lk + 2][lm] = b4.z; Bs[lk + 3][lm] = b4.w;
        __syncthreads();

        #pragma unroll
        for (int kk = 0; kk < 16; kk++) {
            float4 av = *(const float4*)&As[kk][ty * 4];
            ulonglong2 bp = *(const ulonglong2*)&Bs[kk][tx * 4];
            unsigned long long s0 = splat2(av.x);
            unsigned long long s1 = splat2(av.y);
            unsigned long long s2 = splat2(av.z);
            unsigned long long s3 = splat2(av.w);
            acc[0][0] = ffma2(s0, bp.x, acc[0][0]); acc[0][1] = ffma2(s0, bp.y, acc[0][1]);
            acc[1][0] = ffma2(s1, bp.x, acc[1][0]); acc[1][1] = ffma2(s1, bp.y, acc[1][1]);
            acc[2][0] = ffma2(s2, bp.x, acc[2][0]); acc[2][1] = ffma2(s2, bp.y, acc[2][1]);
            acc[3][0] = ffma2(s3, bp.x, acc[3][0]); acc[3][1] = ffma2(s3, bp.y, acc[3][1]);
        }
        __syncthreads();
    }

    #pragma unroll
    for (int r = 0; r < 4; r++) {
        float2 p0 = unpack2(acc[r][0]);
        float2 p1 = unpack2(acc[r][1]);
        float4 o; o.x = p0.x; o.y = p0.y; o.z = p1.x; o.w = p1.y;
        *(float4*)&Cbase[(ty * 4 + r) * ldc + tx * 4] = o;
    }
}

// tilde (bid<512): T[m][n][h] = sum_d (Q[m][n*64+d]+vpos[n*64+d]) * Wr[h][n*64+d]
// ac (bid>=512):   AC[m][n][j] = sum_d (Q[m][n*64+d]+upos[n*64+d]) * K[b][j][n*64+d]
__global__ void tac_kernel(const float* __restrict__ Wr,
                           const float* __restrict__ vpos,
                           const float* __restrict__ upos)
{
    const int bid = blockIdx.x;
    if (bid < 512) {
        const int n    = bid >> 6;
        const int rest = bid & 63;
        const int h0   = (rest & 7) * 64;
        const int m0   = (rest >> 3) * 64;
        nt64_body(g_Q + m0 * 512 + n * 64, vpos + n * 64,
                  Wr + h0 * 512 + n * 64,
                  g_T + (m0 * 8 + n) * 512 + h0, 4096);
    } else {
        const int r    = bid - 512;
        const int n    = r >> 5;
        const int rest = r & 31;
        const int j0   = (rest & 3) * 64;
        const int q    = rest >> 2;          // 0..7
        const int b    = q >> 2;
        const int i0   = (q & 3) * 64;
        nt64_body(g_Q + (b * 256 + i0) * 512 + n * 64, upos + n * 64,
                  g_K + (b * 256 + j0) * 512 + n * 64,
                  g_AC + ((b * 256 + i0) * 8 + n) * 256 + j0, 2048);
    }
}

// ---------------- attn: warp-autonomous scores + softmax -> P ----------------
// 128 threads / 4 warps per CTA, 2 CTAs/SM. Warp w owns j in [w*64, w*64+64),
// 16 groups of 4 j, per-warp cp.async double buffer, no block barriers in the
// mainloop. Lane covers h float4 indices {lane + 32t, t=0..3} for all 8 n and
// 4 j; merged butterfly leaves lane L with score (n=L>>2, jj=L&3).
#define JG        4
#define NGRP      16
#define WBUF      (2 * JG * 512)            // 4096 floats per warp (16 KB)
#define OFF_T     (4 * WBUF)                // 16384
#define OFF_SS    (OFF_T + 4096)            // 20480
#define ATTN_SMEM ((OFF_SS + 2080 + 16) * 4)  // 90304 bytes -> 2 CTAs/SM

__device__ __forceinline__ void attn_issue_group(float* mybuf, const float* rowsrc,
                                                 int lane, int g)
{
    float* dst = mybuf + (g & 1) * (JG * 512);
    const int r  = lane >> 3;
    const int c0 = lane & 7;
    const char* src = (const char*)(rowsrc + r * 512);
    uint32_t s = (uint32_t)__cvta_generic_to_shared(dst + r * 512);
    #pragma unroll
    for (int t = 0; t < 16; t++)
        cpasync16(s + (c0 + t * 8) * 16, src + (c0 + t * 8) * 16);
    cpasync_commit();
}

__global__ __launch_bounds__(128, 2)
void attn_kernel(const float* __restrict__ rpe,
                 const int* __restrict__ seq_len,
                 const int* __restrict__ lex_num)
{
    extern __shared__ __align__(16) float smem[];
    float* T_s = smem + OFF_T;
    float* ss  = smem + OFF_SS;
    __shared__ int s_limit;

    const int tid  = threadIdx.x;     // 0..127
    const int m    = blockIdx.x;
    const int b    = m >> 8;
    const int w    = tid >> 5;        // 0..3
    const int lane = tid & 31;
    const int jw   = w * 64;

    const float* rpe_m = rpe + (size_t)m * 256 * 512;
    float* mybuf = smem + w * WBUF;

    attn_issue_group(mybuf, rpe_m + (size_t)(jw + 0 * JG) * 512, lane, 0);
    attn_issue_group(mybuf, rpe_m + (size_t)(jw + 1 * JG) * 512, lane, 1);

    // T rows for this m: 1024 float4, 128 threads x 8
    {
        const float4* src = (const float4*)(g_T + (size_t)m * 4096);
        float4* dst = (float4*)T_s;
        #pragma unroll
        for (int t = 0; t < 8; t++)
            dst[tid + 128 * t] = src[tid + 128 * t];
    }
    if (tid == 0) s_limit = seq_len[b] + lex_num[0];
    __syncthreads();

    // ---- mainloop: 16 groups, no block barriers ----
    for (int g = 0; g < NGRP; g++) {
        // ledger: g<15 has one younger group in flight -> wait<1>; g==15 -> wait<0>
        if (g < NGRP - 1) cpasync_wait<1>(); else cpasync_wait<0>();
        __syncwarp();

        const float* rb = mybuf + (g & 1) * (JG * 512);
        unsigned long long acc[32] = {};
        #pragma unroll
        for (int t = 0; t < 4; t++) {
            const int f4 = (lane + t * 32) * 4;
            ulonglong2 rj[JG];
            #pragma unroll
            for (int jj = 0; jj < JG; jj++)
                rj[jj] = *(const ulonglong2*)(rb + jj * 512 + f4);
            #pragma unroll
            for (int n = 0; n < 8; n++) {
                ulonglong2 tv = *(const ulonglong2*)(T_s + n * 512 + f4);
                #pragma unroll
                for (int jj = 0; jj < JG; jj++) {
                    acc[n * 4 + jj] = ffma2(rj[jj].x, tv.x, acc[n * 4 + jj]);
                    acc[n * 4 + jj] = ffma2(rj[jj].y, tv.y, acc[n * 4 + jj]);
                }
            }
        }

        if (g + 2 < NGRP)
            attn_issue_group(mybuf, rpe_m + (size_t)(jw + (g + 2) * JG) * 512, lane, g + 2);

        float v[32];
        #pragma unroll
        for (int i = 0; i < 32; i++) {
            float2 f2 = unpack2(acc[i]);
            v[i] = f2.x + f2.y;
        }
        #pragma unroll
        for (int s = 16; s >= 1; s >>= 1) {
            #pragma unroll
            for (int i = 0; i < 16; i++) {
                if (i < s) {
                    float send = (lane & s) ? v[i] : v[i + s];
                    float keep = (lane & s) ? v[i + s] : v[i];
                    v[i] = keep + __shfl_xor_sync(0xffffffffu, send, s);
                }
            }
        }
        // lane L: n = L>>2, jj = L&3
        ss[(lane >> 2) * 260 + jw + g * JG + (lane & 3)] = v[0];
    }

    __syncthreads();

    // softmax: warp w handles heads w and w+4; fold in AC, scale, mask
    const int limit = s_limit;
    #pragma unroll
    for (int hh = 0; hh < 2; hh++) {
        const int n = w + hh * 4;
        float vals[8];
        #pragma unroll
        for (int t = 0; t < 8; t++) {
            int j = lane + 32 * t;
            float raw = ss[n * 260 + j];
            float ac  = g_AC[((size_t)m * 8 + n) * 256 + j];
            vals[t] = (j < limit) ? (raw + ac) * 0.125f : -1e15f;
        }
        float mx = vals[0];
        #pragma unroll
        for (int t = 1; t < 8; t++) mx = fmaxf(mx, vals[t]);
        #pragma unroll
        for (int o = 16; o; o >>= 1) mx = fmaxf(mx, __shfl_xor_sync(0xffffffffu, mx, o));
        float sum = 0.f;
        #pragma unroll
        for (int t = 0; t < 8; t++) { vals[t] = __expf(vals[t] - mx); sum += vals[t]; }
        #pragma unroll
        for (int o = 16; o; o >>= 1) sum += __shfl_xor_sync(0xffffffffu, sum, o);
        float inv = 1.f / sum;
        #pragma unroll
        for (int t = 0; t < 8; t++) ss[n * 260 + lane + 32 * t] = vals[t] * inv;
    }
    __syncthreads();

    // write P: 512 float4, 128 threads x 4
    {
        float4* P4 = (float4*)g_P + (size_t)m * 512;
        #pragma unroll
        for (int t = 0; t < 4; t++) {
            int f = tid + 128 * t;
            int n = f >> 6;
            int c4 = f & 63;
            P4[f] = *(const float4*)&ss[n * 260 + c4 * 4];
        }
    }
}

// ---------------- ctx: CTX[m][n*64+d] = sum_j P[m][n][j] * V[b][j][n*64+d] ----------------
// R8 version: 32-i tiles, grid (8, 8, 2), 256 threads, 2x4 microtile.
__global__ void ctx_kernel()
{
    __shared__ __align__(16) float Ps[64][34];
    __shared__ __align__(16) float Vs[64][68];

    const int tid = threadIdx.x;
    const int tx = tid & 15, ty = tid >> 4;
    const int i0 = blockIdx.x * 32;
    const int n  = blockIdx.y;
    const int b  = blockIdx.z;

    unsigned long long acc[2][2] = {};

    for (int j0 = 0; j0 < 256; j0 += 64) {
        {
            const int li = tid >> 3;
            #pragma unroll
            for (int q = 0; q < 2; q++) {
                int jf = (tid & 7) + q * 8;
                float4 p4 = *(const float4*)&g_P[(((size_t)(b * 256 + i0 + li)) * 8 + n) * 256 + j0 + jf * 4];
                Ps[jf * 4 + 0][li] = p4.x;
                Ps[jf * 4 + 1][li] = p4.y;
                Ps[jf * 4 + 2][li] = p4.z;
                Ps[jf * 4 + 3][li] = p4.w;
            }
        }
        {
            const int lj = tid >> 2;
            const int fl = tid & 3;
            #pragma unroll
            for (int q = 0; q < 4; q++) {
                int f4 = fl + q * 4;
                float4 v4 = *(const float4*)&g_V[(size_t)(b * 256 + j0 + lj) * 512 + n * 64 + f4 * 4];
                *(float4*)&Vs[lj][f4 * 4] = v4;
            }
        }
        __syncthreads();

        #pragma unroll 16
        for (int j = 0; j < 64; j++) {
            float2 av = *(const float2*)&Ps[j][ty * 2];
            ulonglong2 bp = *(const ulonglong2*)&Vs[j][tx * 4];
            unsigned long long s0 = splat2(av.x);
            unsigned long long s1 = splat2(av.y);
            acc[0][0] = ffma2(s0, bp.x, acc[0][0]); acc[0][1] = ffma2(s0, bp.y, acc[0][1]);
            acc[1][0] = ffma2(s1, bp.x, acc[1][0]); acc[1][1] = ffma2(s1, bp.y, acc[1][1]);
        }
        __syncthreads();
    }

    #pragma unroll
    for (int r = 0; r < 2; r++) {
        float2 p0 = unpack2(acc[r][0]);
        float2 p1 = unpack2(acc[r][1]);
        float4 o; o.x = p0.x; o.y = p0.y; o.z = p1.x; o.w = p1.y;
        *(float4*)&g_CTX[(size_t)(b * 256 + i0 + ty * 2 + r) * 512 + n * 64 + tx * 4] = o;
    }
}

// ---------------- launch ----------------
extern "C" void kernel_launch(void* const* d_in, const int* in_sizes, int n_in,
                              void* d_out, int out_size)
{
    const float* key     = (const float*)d_in[0];
    const float* query   = (const float*)d_in[1];
    const float* value   = (const float*)d_in[2];
    const int*   seq_len = (const int*)  d_in[3];
    const int*   lex_num = (const int*)  d_in[4];
    const float* rpe     = (const float*)d_in[7];
    const float* Wk      = (const float*)d_in[8];
    const float* bk      = (const float*)d_in[9];
    const float* Wq      = (const float*)d_in[10];
    const float* bq      = (const float*)d_in[11];
    const float* Wv      = (const float*)d_in[12];
    const float* bv      = (const float*)d_in[13];
    const float* Wr      = (const float*)d_in[14];
    const float* upos    = (const float*)d_in[16];
    const float* vpos    = (const float*)d_in[17];
    const float* Wf      = (const float*)d_in[18];
    const float* bf      = (const float*)d_in[19];
    float* out = (float*)d_out;

    static bool attr_set = false;
    if (!attr_set) {
        cudaFuncSetAttribute(attn_kernel,
                             cudaFuncAttributeMaxDynamicSharedMemorySize, ATTN_SMEM);
        attr_set = true;
    }

    proj_kernel <<<dim3(8, 16, 3), 128>>>(key, query, value, Wk, bk, Wq, bq, Wv, bv);
    tac_kernel  <<<dim3(768), 256>>>(Wr, vpos, upos);
    attn_kernel <<<dim3(BB * LL), 128, ATTN_SMEM>>>(rpe, seq_len, lex_num);
    ctx_kernel  <<<dim3(8, 8, 2), 256>>>();
    final_kernel<<<dim3(8, 16), 128>>>(Wf, bf, out);
}